// round 14
// baseline (speedup 1.0000x reference)
#include <cuda_runtime.h>
#include <cuda_fp16.h>
#include <math.h>
#include <stdint.h>

#define B_   8
#define S_   512
#define DIN  1024
#define DOUT 1024
#define H_   8
#define DATT 128
#define NTOK (B_ * S_)   // 4096

// ---------------- device scratch (no allocation allowed) ----------------
__device__ __align__(16) float    g_colsum[B_ * DOUT];      // column sums (fallback)
__device__ __align__(16) float    g_s2[B_ * H_ * S_];       // raw attention logits
__device__ __align__(16) uint16_t g_xf[NTOK * DIN];         // x fp16
__device__ __align__(16) uint16_t g_wt[DOUT * DIN];         // W^T fp16 [n][k]
__device__ __align__(16) uint16_t g_xst[DOUT * NTOK];       // xp^T fp16 [c][token]
__device__ __align__(16) uint16_t g_adjf[B_ * S_ * S_];     // valid adjacency fp16

// ---------------------------- helpers ----------------------------
__device__ __forceinline__ uint32_t smem_u32(const void* p) {
    uint32_t a;
    asm("{ .reg .u64 t; cvta.to.shared.u64 t, %1; cvt.u32.u64 %0, t; }" : "=r"(a) : "l"(p));
    return a;
}
__device__ __forceinline__ uint32_t swz(uint32_t off) { return off ^ ((off >> 3) & 0x70); }

__device__ __forceinline__ void cpasync16(uint32_t smem, const void* gmem) {
    asm volatile("cp.async.cg.shared.global [%0], [%1], 16;" :: "r"(smem), "l"(gmem));
}
__device__ __forceinline__ void cp_commit() {
    asm volatile("cp.async.commit_group;" ::: "memory");
}
template <int N>
__device__ __forceinline__ void cp_wait() {
    asm volatile("cp.async.wait_group %0;" :: "n"(N) : "memory");
}
__device__ __forceinline__ void ldsm4(uint32_t& r0, uint32_t& r1, uint32_t& r2, uint32_t& r3,
                                      uint32_t addr) {
    asm volatile("ldmatrix.sync.aligned.m8n8.x4.shared.b16 {%0,%1,%2,%3}, [%4];"
                 : "=r"(r0), "=r"(r1), "=r"(r2), "=r"(r3) : "r"(addr));
}
__device__ __forceinline__ void mma_fp16(float* c, const uint32_t* a, uint32_t b0, uint32_t b1) {
    asm volatile(
        "mma.sync.aligned.m16n8k16.row.col.f32.f16.f16.f32 "
        "{%0,%1,%2,%3}, {%4,%5,%6,%7}, {%8,%9}, {%0,%1,%2,%3};"
        : "+f"(c[0]), "+f"(c[1]), "+f"(c[2]), "+f"(c[3])
        : "r"(a[0]), "r"(a[1]), "r"(a[2]), "r"(a[3]), "r"(b0), "r"(b1));
}
__device__ __forceinline__ uint16_t h_bits(float f) {
    __half h = __float2half_rn(f);
    return *(uint16_t*)&h;
}
__device__ __forceinline__ uint32_t h2_bits(float x0, float x1) {
    return (uint32_t)h_bits(x0) | ((uint32_t)h_bits(x1) << 16);
}
__device__ __forceinline__ void sts16(uint32_t addr, uint16_t v) {
    asm volatile("st.shared.u16 [%0], %1;" :: "r"(addr), "h"(v));
}
__device__ __forceinline__ void sts128(uint32_t addr, uint4 v) {
    asm volatile("st.shared.v4.b32 [%0], {%1,%2,%3,%4};"
                 :: "r"(addr), "r"(v.x), "r"(v.y), "r"(v.z), "r"(v.w));
}
__device__ __forceinline__ void lds128(uint4& v, uint32_t addr) {
    asm volatile("ld.shared.v4.u32 {%0,%1,%2,%3}, [%4];"
                 : "=r"(v.x), "=r"(v.y), "=r"(v.z), "=r"(v.w) : "r"(addr));
}
__device__ __forceinline__ void lds32(uint32_t& v, uint32_t addr) {
    asm volatile("ld.shared.u32 %0, [%1];" : "=r"(v) : "r"(addr));
}
__device__ __forceinline__ uint32_t hmul2(uint32_t a, uint32_t b) {
    uint32_t d;
    asm("mul.rn.f16x2 %0, %1, %2;" : "=r"(d) : "r"(a), "r"(b));
    return d;
}
__device__ __forceinline__ uint32_t hadd2(uint32_t a, uint32_t b) {
    uint32_t d;
    asm("add.rn.f16x2 %0, %1, %2;" : "=r"(d) : "r"(a), "r"(b));
    return d;
}

// ============================================================================
// Kernel 1 (merged pre-pass)
// ============================================================================
__global__ __launch_bounds__(256) void prepass(const float* __restrict__ x,
                                               const float* __restrict__ W,
                                               const int* __restrict__ adj,
                                               const float* __restrict__ mask) {
    __shared__ float tile[32][33];
    int blk = blockIdx.x, tid = threadIdx.x;
    if (blk < 2048) {
        size_t base = ((size_t)blk * 256 + tid) * 8;
        float4 v0 = *(const float4*)(x + base);
        float4 v1 = *(const float4*)(x + base + 4);
        *(uint4*)(g_xf + base) = make_uint4(h2_bits(v0.x, v0.y), h2_bits(v0.z, v0.w),
                                            h2_bits(v1.x, v1.y), h2_bits(v1.z, v1.w));
    } else if (blk < 3072) {
        int bb = blk - 2048;
        int n0 = (bb & 31) * 32, k0 = (bb >> 5) * 32;
        int tx = tid & 31, ty = tid >> 5;
#pragma unroll
        for (int i = 0; i < 4; i++)
            tile[ty + i * 8][tx] = W[(size_t)(k0 + ty + i * 8) * DOUT + n0 + tx];
        __syncthreads();
#pragma unroll
        for (int i = 0; i < 4; i++) {
            int n = n0 + ty + i * 8, k = k0 + tx;
            g_wt[(size_t)n * DIN + k] = h_bits(tile[tx][ty + i * 8]);
        }
    } else if (blk < 4096) {
        size_t base = ((size_t)(blk - 3072) * 256 + tid) * 8;
        int bi = (int)(base >> 9);
        uint32_t one = (mask[bi] > 0.f) ? 0x3C00u : 0u;   // fp16 1.0
        int4 a0 = *(const int4*)(adj + base);
        int4 a1 = *(const int4*)(adj + base + 4);
        uint32_t p0 = ((a0.x > 0) ? one : 0u) | (((a0.y > 0) ? one : 0u) << 16);
        uint32_t p1 = ((a0.z > 0) ? one : 0u) | (((a0.w > 0) ? one : 0u) << 16);
        uint32_t p2 = ((a1.x > 0) ? one : 0u) | (((a1.y > 0) ? one : 0u) << 16);
        uint32_t p3 = ((a1.z > 0) ? one : 0u) | (((a1.w > 0) ? one : 0u) << 16);
        *(uint4*)(g_adjf + base) = make_uint4(p0, p1, p2, p3);
    } else {
        g_colsum[(blk - 4096) * 256 + tid] = 0.f;
    }
}

// ============================================================================
// Kernel 2: projection GEMM, BM=128 BN=256 BK=128, 512 thr, 2-stage cp.async
//   Epilogue: smem transpose -> g_xst fp16, colsum atomics, AND s2 logits
// ============================================================================
#define PROJ_STAGE 98304          // A 2x16K + B 2x32K
#define PROJ_SMEM (2 * PROJ_STAGE + 2048)
__global__ __launch_bounds__(512) void proj_mma(const float* __restrict__ attw) {
    extern __shared__ char dsm[];
    uint32_t sb = (smem_u32(dsm) + 1023) & ~1023u;

    int tid = threadIdx.x, lane = tid & 31, wid = tid >> 5;
    int wm = wid & 3, wn = wid >> 2;  // 4 x 4 warps, each 32m x 64n
    int m_base = blockIdx.y * 128, n_base = blockIdx.x * 256;

    int srow = tid >> 3, skg = tid & 7;

    auto stage = [&](int ck, int s) {
        uint32_t base = sb + (uint32_t)s * PROJ_STAGE;
#pragma unroll
        for (int sub = 0; sub < 2; sub++) {
#pragma unroll
            for (int it = 0; it < 2; it++) {  // A: 128 rows
                int row = srow + it * 64;
                uint32_t so = swz((uint32_t)(row * 128 + skg * 16));
                size_t ga = (size_t)(m_base + row) * DIN + ck * 128 + sub * 64 + skg * 8;
                cpasync16(base + sub * 16384 + so, g_xf + ga);
            }
#pragma unroll
            for (int it = 0; it < 4; it++) {  // B: 256 rows
                int row = srow + it * 64;
                uint32_t so = swz((uint32_t)(row * 128 + skg * 16));
                size_t gb = (size_t)(n_base + row) * DIN + ck * 128 + sub * 64 + skg * 8;
                cpasync16(base + 32768 + sub * 32768 + so, g_wt + gb);
            }
        }
        cp_commit();
    };

    float acc[2][8][4] = {};

    stage(0, 0);
    for (int ck = 0; ck < 8; ck++) {
        if (ck + 1 < 8) {
            stage(ck + 1, (ck + 1) & 1);
            cp_wait<1>();
        } else {
            cp_wait<0>();
        }
        __syncthreads();
        uint32_t cbase = sb + (uint32_t)(ck & 1) * PROJ_STAGE;
#pragma unroll
        for (int sub = 0; sub < 2; sub++) {
            uint32_t AS = cbase + sub * 16384;
            uint32_t BS = cbase + 32768 + sub * 32768;
#pragma unroll
            for (int ks = 0; ks < 4; ks++) {
                uint32_t af[2][4];
#pragma unroll
                for (int mt = 0; mt < 2; mt++) {
                    int r = wm * 32 + mt * 16 + (lane & 15);
                    int kb = ks * 32 + (lane >> 4) * 16;
                    uint32_t off = swz((uint32_t)(r * 128 + kb));
                    ldsm4(af[mt][0], af[mt][1], af[mt][2], af[mt][3], AS + off);
                }
#pragma unroll
                for (int nq = 0; nq < 4; nq++) {
                    int r = wn * 64 + nq * 16 + (lane & 7) + ((lane >> 4) & 1) * 8;
                    int kb = ks * 32 + ((lane >> 3) & 1) * 16;
                    uint32_t off = swz((uint32_t)(r * 128 + kb));
                    uint32_t bs[4];
                    ldsm4(bs[0], bs[1], bs[2], bs[3], BS + off);
#pragma unroll
                    for (int mt = 0; mt < 2; mt++) {
                        mma_fp16(acc[mt][nq * 2],     af[mt], bs[0], bs[1]);
                        mma_fp16(acc[mt][nq * 2 + 1], af[mt], bs[2], bs[3]);
                    }
                }
            }
        }
        __syncthreads();
    }

    // ---- epilogue ----
    const int RS = 136;              // transpose row stride (halves): 128 + 8 pad
    uint32_t S2P = sb + 69632;       // 2 heads x 128 rows of float partials

    float p[2][2] = {};
#pragma unroll
    for (int mt = 0; mt < 2; mt++)
#pragma unroll
        for (int nt = 0; nt < 8; nt++) {
            int c = wn * 64 + nt * 8 + (lane & 3) * 2;
            float w0 = __ldg(attw + DATT + (c & 127));
            float w1 = __ldg(attw + DATT + ((c + 1) & 127));
            p[mt][0] += acc[mt][nt][0] * w0 + acc[mt][nt][1] * w1;
            p[mt][1] += acc[mt][nt][2] * w0 + acc[mt][nt][3] * w1;
        }
#pragma unroll
    for (int mt = 0; mt < 2; mt++) {
#pragma unroll
        for (int o = 1; o < 4; o <<= 1) {
            p[mt][0] += __shfl_xor_sync(0xFFFFFFFFu, p[mt][0], o);
            p[mt][1] += __shfl_xor_sync(0xFFFFFFFFu, p[mt][1], o);
        }
    }

    if (tid < 256) *(float*)(dsm + (S2P - smem_u32(dsm)) + tid * 4) = 0.f;

#pragma unroll
    for (int mt = 0; mt < 2; mt++)
#pragma unroll
        for (int nt = 0; nt < 8; nt++) {
            int r = wm * 32 + mt * 16 + (lane >> 2);
            int c = wn * 64 + nt * 8 + (lane & 3) * 2;
            float* a4 = acc[mt][nt];
            sts16(sb + (uint32_t)(c * RS + r) * 2,            h_bits(a4[0]));
            sts16(sb + (uint32_t)((c + 1) * RS + r) * 2,      h_bits(a4[1]));
            sts16(sb + (uint32_t)(c * RS + r + 8) * 2,        h_bits(a4[2]));
            sts16(sb + (uint32_t)((c + 1) * RS + r + 8) * 2,  h_bits(a4[3]));
        }
    __syncthreads();

    if ((lane & 3) == 0) {
        int head = wn >> 1;
        int r0 = wm * 32 + (lane >> 2);
        float* s2p = (float*)(dsm + (S2P - smem_u32(dsm)));
#pragma unroll
        for (int mt = 0; mt < 2; mt++) {
            atomicAdd(&s2p[head * 128 + r0 + mt * 16], p[mt][0]);
            atomicAdd(&s2p[head * 128 + r0 + mt * 16 + 8], p[mt][1]);
        }
    }

    int b = m_base >> 9;
#pragma unroll
    for (int it = 0; it < 8; it++) {
        int task = it * 512 + tid;      // 4096 tasks: 256 c x 16 token-groups
        int c = task >> 4, g = task & 15;
        uint4 v;
        lds128(v, sb + (uint32_t)(c * RS + g * 8) * 2);
        *(uint4*)(g_xst + (size_t)(n_base + c) * NTOK + m_base + g * 8) = v;
        float2 f0 = __half22float2(*(__half2*)&v.x);
        float2 f1 = __half22float2(*(__half2*)&v.y);
        float2 f2 = __half22float2(*(__half2*)&v.z);
        float2 f3 = __half22float2(*(__half2*)&v.w);
        float s = f0.x + f0.y + f1.x + f1.y + f2.x + f2.y + f3.x + f3.y;
#pragma unroll
        for (int o = 8; o; o >>= 1) s += __shfl_xor_sync(0xFFFFFFFFu, s, o);
        if ((tid & 15) == 0) atomicAdd(&g_colsum[(b << 10) + n_base + c], s);
    }
    __syncthreads();

    if (tid < 256) {
        int head = tid >> 7, row = tid & 127;
        int h = (n_base >> 7) + head;
        float v = *(float*)(dsm + (S2P - smem_u32(dsm)) + tid * 4);
        g_s2[(size_t)(b * H_ + h) * S_ + (m_base & 511) + row] = v;
    }
}

// ============================================================================
// Kernel 3: attention GEMM, 512 thr, BM=256(i) BN=128(c) BK=128, grid=128
//   Prologue computes e2 = mask*exp(s2-max) in-kernel (expk fused).
//   e2 folded into A fragments; denominator from folded fragments via
//   f16x2 adds + fp32 accumulation (NO denominator MMAs); fused normalize.
// ============================================================================
#define ATT_STAGE 98304           // adj 2x32K + xst 2x16K
#define ATT_SMEM (2048 + 2 * ATT_STAGE + 1024)
__global__ __launch_bounds__(512) void att_mma(const float* __restrict__ mask,
                                               float* __restrict__ out) {
    extern __shared__ char dsm[];
    uint32_t sb = (smem_u32(dsm) + 1023) & ~1023u;
    uint32_t E2 = sb;                      // 1 KB: e2 fp16
    uint32_t stage0 = sb + 2048;

    int tid = threadIdx.x, lane = tid & 31, wid = tid >> 5;
    int wm = wid & 7, wn = wid >> 3;   // 8 x 2 warps: 32 i x 64 c each
    int h = blockIdx.x, i0 = blockIdx.y * 256, b = blockIdx.z;
    int c0 = h * DATT;

    int srow = tid >> 3, skg = tid & 7;

    auto stage = [&](int ck, int s) {
        uint32_t base = stage0 + (uint32_t)s * ATT_STAGE;
#pragma unroll
        for (int sub = 0; sub < 2; sub++) {
#pragma unroll
            for (int it = 0; it < 4; it++) {   // adjacency: 256 rows
                int row = srow + it * 64;
                uint32_t so = swz((uint32_t)(row * 128 + skg * 16));
                size_t ga = (size_t)(b * S_ + i0 + row) * S_ + ck * 128 + sub * 64 + skg * 8;
                cpasync16(base + sub * 32768 + so, g_adjf + ga);
            }
#pragma unroll
            for (int it = 0; it < 2; it++) {   // xst: 128 rows
                int row = srow + it * 64;
                uint32_t so = swz((uint32_t)(row * 128 + skg * 16));
                size_t gb = (size_t)(c0 + row) * NTOK + b * S_ + ck * 128 + sub * 64 + skg * 8;
                cpasync16(base + 65536 + sub * 16384 + so, g_xst + gb);
            }
        }
        cp_commit();
    };

    // stage chunk 0 first, then compute e2 while it flies
    stage(0, 0);
    {
        float* red = (float*)(dsm + (sb + 1024 - smem_u32(dsm)));
        float v = g_s2[(size_t)(b * H_ + h) * S_ + tid];
        float m = v;
#pragma unroll
        for (int o = 16; o; o >>= 1) m = fmaxf(m, __shfl_xor_sync(0xFFFFFFFFu, m, o));
        if (lane == 0) red[wid] = m;
        __syncthreads();
        if (wid == 0) {
            float t = (lane < 16) ? red[lane] : -INFINITY;
#pragma unroll
            for (int o = 8; o; o >>= 1) t = fmaxf(t, __shfl_xor_sync(0xFFFFFFFFu, t, o));
            if (lane == 0) red[0] = t;
        }
        __syncthreads();
        m = red[0];
        float mj = mask[b * S_ + tid] > 0.f ? 1.f : 0.f;
        sts16(E2 + tid * 2, h_bits(mj * expf(v - m)));
    }

    float acc[2][8][4] = {};
    float2 accd[2][2] = {};   // [mt][row r / row r+8] fp32 denominator partials

    for (int kc = 0; kc < 4; kc++) {
        if (kc + 1 < 4) {
            stage(kc + 1, (kc + 1) & 1);
            cp_wait<1>();
        } else {
            cp_wait<0>();
        }
        __syncthreads();
        uint32_t cbase = stage0 + (uint32_t)(kc & 1) * ATT_STAGE;
#pragma unroll
        for (int sub = 0; sub < 2; sub++) {
            uint32_t AD = cbase + sub * 32768;
            uint32_t BS = cbase + 65536 + sub * 16384;
#pragma unroll
            for (int ks = 0; ks < 4; ks++) {
                uint32_t ad[2][4];
#pragma unroll
                for (int mt = 0; mt < 2; mt++) {
                    int r = wm * 32 + mt * 16 + (lane & 15);
                    int kb = ks * 32 + (lane >> 4) * 16;
                    ldsm4(ad[mt][0], ad[mt][1], ad[mt][2], ad[mt][3],
                          AD + swz((uint32_t)(r * 128 + kb)));
                }
                // fold e2[j] into A fragments (adj in {0,1} -> product exact)
                {
                    int kj = kc * 128 + sub * 64 + ks * 16 + (lane & 3) * 2;
                    uint32_t ea, eb;
                    lds32(ea, E2 + kj * 2);
                    lds32(eb, E2 + kj * 2 + 16);
#pragma unroll
                    for (int mt = 0; mt < 2; mt++) {
                        ad[mt][0] = hmul2(ad[mt][0], ea);
                        ad[mt][1] = hmul2(ad[mt][1], ea);
                        ad[mt][2] = hmul2(ad[mt][2], eb);
                        ad[mt][3] = hmul2(ad[mt][3], eb);
                    }
                }
                // denominator from folded fragments (fma pipe, no MMA):
                //   row r:   ad[0] (k lo) + ad[2] (k hi);  row r+8: ad[1]+ad[3]
#pragma unroll
                for (int mt = 0; mt < 2; mt++) {
                    uint32_t sr  = hadd2(ad[mt][0], ad[mt][2]);
                    uint32_t sr8 = hadd2(ad[mt][1], ad[mt][3]);
                    float2 f = __half22float2(*(__half2*)&sr);
                    accd[mt][0].x += f.x; accd[mt][0].y += f.y;
                    f = __half22float2(*(__half2*)&sr8);
                    accd[mt][1].x += f.x; accd[mt][1].y += f.y;
                }
#pragma unroll
                for (int nq = 0; nq < 4; nq++) {
                    int r = wn * 64 + nq * 16 + (lane & 7) + ((lane >> 4) & 1) * 8;
                    int kb = ks * 32 + ((lane >> 3) & 1) * 16;
                    uint32_t off = swz((uint32_t)(r * 128 + kb));
                    uint32_t bs[4];
                    ldsm4(bs[0], bs[1], bs[2], bs[3], BS + off);
#pragma unroll
                    for (int mt = 0; mt < 2; mt++) {
                        mma_fp16(acc[mt][nq * 2],     ad[mt], bs[0], bs[1]);
                        mma_fp16(acc[mt][nq * 2 + 1], ad[mt], bs[2], bs[3]);
                    }
                }
            }
        }
        __syncthreads();
    }

    // epilogue: denom via quad shfl-reduce, normalize + fallback
    const float* cs = g_colsum + (b << 10);
#pragma unroll
    for (int mt = 0; mt < 2; mt++) {
        int r0 = i0 + wm * 32 + mt * 16 + (lane >> 2);
        float d0 = accd[mt][0].x + accd[mt][0].y;
        float d1 = accd[mt][1].x + accd[mt][1].y;
        d0 += __shfl_xor_sync(0xFFFFFFFFu, d0, 1);
        d0 += __shfl_xor_sync(0xFFFFFFFFu, d0, 2);
        d1 += __shfl_xor_sync(0xFFFFFFFFu, d1, 1);
        d1 += __shfl_xor_sync(0xFFFFFFFFu, d1, 2);
        float q0 = (d0 > 0.f) ? (1.0f / d0) : 0.f;
        float q1 = (d1 > 0.f) ? (1.0f / d1) : 0.f;
#pragma unroll
        for (int nt = 0; nt < 8; nt++) {
            int c = c0 + wn * 64 + nt * 8 + (lane & 3) * 2;
            float* a4 = acc[mt][nt];
            float2 o0, o1;
            if (d0 > 0.f) { o0 = make_float2(a4[0] * q0, a4[1] * q0); }
            else {
                float2 f = *(const float2*)(cs + c);
                o0 = make_float2(f.x * (1.0f / S_), f.y * (1.0f / S_));
            }
            if (d1 > 0.f) { o1 = make_float2(a4[2] * q1, a4[3] * q1); }
            else {
                float2 f = *(const float2*)(cs + c);
                o1 = make_float2(f.x * (1.0f / S_), f.y * (1.0f / S_));
            }
            *(float2*)(out + (size_t)(b * S_ + r0) * DOUT + c) = o0;
            *(float2*)(out + (size_t)(b * S_ + r0 + 8) * DOUT + c) = o1;
        }
    }
}

// ============================================================================
extern "C" void kernel_launch(void* const* d_in, const int* in_sizes, int n_in,
                              void* d_out, int out_size) {
    const float* x    = (const float*)d_in[0];
    const float* mask = (const float*)d_in[1];
    const int*   adj  = (const int*)d_in[2];
    const float* W    = (const float*)d_in[3];
    const float* attw = (const float*)d_in[4];
    float* out = (float*)d_out;

    cudaFuncSetAttribute(proj_mma, cudaFuncAttributeMaxDynamicSharedMemorySize, PROJ_SMEM);
    cudaFuncSetAttribute(att_mma, cudaFuncAttributeMaxDynamicSharedMemorySize, ATT_SMEM);

    prepass<<<4128, 256>>>(x, W, adj, mask);
    proj_mma<<<dim3(DOUT / 256, NTOK / 128), 512, PROJ_SMEM>>>(attw);
    att_mma<<<dim3(H_, S_ / 256, B_), 512, ATT_SMEM>>>(mask, out);
}